// round 3
// baseline (speedup 1.0000x reference)
#include <cuda_runtime.h>
#include <math.h>

#define DIMC 512
#define NHEADS 8
#define HD 64
#define FSZ 56
#define NTOK 3136
#define KTOK 784
#define BATCH 4
#define ATT_SCALE 0.125f
#define LN_EPS 1e-5f
#define POSW 111

// ---------------- scratch ----------------
__device__ float g_bias[NTOK * KTOK];                    // 9.8 MB  [n][m]
__device__ float g_q[BATCH * NHEADS * NTOK * HD];        // 25.7 MB [bh][n][d]
__device__ float g_xr[BATCH * KTOK * DIMC];              // 6.4 MB  [b][m][c] (conv out, then LN'd in place)
__device__ float g_k[BATCH * NHEADS * KTOK * HD];        // 3.2 MB  [bh][m][d]
__device__ float g_v[BATCH * NHEADS * KTOK * HD];        // 3.2 MB
__device__ float g_ao[BATCH * NTOK * DIMC];              // 25.7 MB [b][n][c]

// ---------------- bias precompute ----------------
__global__ void bias_kernel(const float* __restrict__ pos, const int* __restrict__ rel) {
    int i = blockIdx.x * 256 + threadIdx.x;
    if (i >= NTOK * KTOK) return;
    int n = i / KTOK, m = i % KTOK;
    long long base = ((long long)n * NTOK + m) * 2;
    int r0 = rel[base], r1 = rel[base + 1];
    g_bias[i] = pos[r0 * POSW + r1];
}

// ---------------- GEMM Q: per batch, C[n][c'] = sum_c x[b][c][n] * Wq[c][c'] ----------------
// A[m][k] = x[b][k][m] (k-strided), B row-major. M=3136, N=512, K=512.
__global__ void gemm_q(const float* __restrict__ x, const float* __restrict__ Wq) {
    __shared__ __align__(16) float As[16][64];
    __shared__ __align__(16) float Bs[16][64];
    int b = blockIdx.z;
    int m0 = blockIdx.y * 64, n0 = blockIdx.x * 64;
    int tid = threadIdx.x;
    int tx = tid & 15, ty = tid >> 4;
    const float* xb = x + (long long)b * DIMC * NTOK;
    float acc[4][4] = {};
    int la_k = tid >> 4;            // 0..15
    int la_m = (tid & 15) * 4;      // 0..60
    for (int k0 = 0; k0 < DIMC; k0 += 16) {
        *(float4*)&As[la_k][la_m] =
            *(const float4*)&xb[(long long)(k0 + la_k) * NTOK + m0 + la_m];
        *(float4*)&Bs[la_k][la_m] =
            *(const float4*)&Wq[(k0 + la_k) * DIMC + n0 + la_m];
        __syncthreads();
#pragma unroll
        for (int kk = 0; kk < 16; kk++) {
            float4 a = *(float4*)&As[kk][ty * 4];
            float4 bq = *(float4*)&Bs[kk][tx * 4];
            float av[4] = {a.x, a.y, a.z, a.w};
            float bv[4] = {bq.x, bq.y, bq.z, bq.w};
#pragma unroll
            for (int i = 0; i < 4; i++)
#pragma unroll
                for (int j = 0; j < 4; j++) acc[i][j] += av[i] * bv[j];
        }
        __syncthreads();
    }
#pragma unroll
    for (int i = 0; i < 4; i++) {
        int m = m0 + ty * 4 + i;
#pragma unroll
        for (int j = 0; j < 4; j++) {
            int n = n0 + tx * 4 + j;
            int h = n >> 6, d = n & 63;
            g_q[(((long long)b * NHEADS + h) * NTOK + m) * HD + d] = acc[i][j];
        }
    }
}

// ---------------- GEMM conv (stride-2 2x2 conv as im2col GEMM) ----------------
// M=784 (m=ph*28+pw), N=512 (o), K=2048 (k=i*4+kh*2+kw)
// A[m][k]=x[b][i][2ph+kh][2pw+kw], B[k][o]=Wsr[o*2048+k] (B transposed)
__global__ void gemm_conv(const float* __restrict__ x, const float* __restrict__ Wsr,
                          const float* __restrict__ b_sr) {
    __shared__ __align__(16) float As[16][64];
    __shared__ __align__(16) float Bs[16][64];
    int b = blockIdx.z;
    int m0 = blockIdx.y * 64, n0 = blockIdx.x * 64;
    int tid = threadIdx.x;
    int tx = tid & 15, ty = tid >> 4;
    const float* xb = x + (long long)b * DIMC * NTOK;
    float acc[4][4] = {};
    int la_k = tid >> 4;            // 0..15 (kk within tile)
    int la_m = (tid & 15) * 4;      // 0..60
    int lb_n = tid >> 2;            // 0..63
    int lb_k = (tid & 3) * 4;       // 0,4,8,12
    for (int k0 = 0; k0 < 2048; k0 += 16) {
        // A gather
        {
            int kk = k0 + la_k;
            int ii = kk >> 2;
            int kh = (kk >> 1) & 1, kw = kk & 1;
            const float* xp = xb + (long long)ii * NTOK;
#pragma unroll
            for (int t = 0; t < 4; t++) {
                int m = m0 + la_m + t;
                float v = 0.f;
                if (m < KTOK) {
                    int ph = m / 28, pw = m - ph * 28;
                    v = xp[(2 * ph + kh) * FSZ + 2 * pw + kw];
                }
                As[la_k][la_m + t] = v;
            }
        }
        // B (transposed source)
        {
            float4 w = *(const float4*)&Wsr[(long long)(n0 + lb_n) * 2048 + k0 + lb_k];
            Bs[lb_k + 0][lb_n] = w.x;
            Bs[lb_k + 1][lb_n] = w.y;
            Bs[lb_k + 2][lb_n] = w.z;
            Bs[lb_k + 3][lb_n] = w.w;
        }
        __syncthreads();
#pragma unroll
        for (int kk = 0; kk < 16; kk++) {
            float4 a = *(float4*)&As[kk][ty * 4];
            float4 bq = *(float4*)&Bs[kk][tx * 4];
            float av[4] = {a.x, a.y, a.z, a.w};
            float bv[4] = {bq.x, bq.y, bq.z, bq.w};
#pragma unroll
            for (int i = 0; i < 4; i++)
#pragma unroll
                for (int j = 0; j < 4; j++) acc[i][j] += av[i] * bv[j];
        }
        __syncthreads();
    }
#pragma unroll
    for (int i = 0; i < 4; i++) {
        int m = m0 + ty * 4 + i;
        if (m >= KTOK) continue;
#pragma unroll
        for (int j = 0; j < 4; j++) {
            int n = n0 + tx * 4 + j;
            g_xr[((long long)b * KTOK + m) * DIMC + n] = acc[i][j] + b_sr[n];
        }
    }
}

// ---------------- LayerNorm over C=512, in place on g_xr ----------------
__global__ void ln_kernel(const float* __restrict__ gamma, const float* __restrict__ beta) {
    int row = blockIdx.x;  // 0..B*KTOK-1
    float* p = g_xr + (long long)row * DIMC;
    int t = threadIdx.x;   // 256
    float v0 = p[t], v1 = p[t + 256];
    float s = v0 + v1, sq = v0 * v0 + v1 * v1;
#pragma unroll
    for (int o = 16; o > 0; o >>= 1) {
        s += __shfl_xor_sync(0xffffffffu, s, o);
        sq += __shfl_xor_sync(0xffffffffu, sq, o);
    }
    __shared__ float rs_[8], rq_[8];
    int lane = t & 31, w = t >> 5;
    if (lane == 0) { rs_[w] = s; rq_[w] = sq; }
    __syncthreads();
    if (t == 0) {
        float S = 0.f, Q = 0.f;
#pragma unroll
        for (int i = 0; i < 8; i++) { S += rs_[i]; Q += rq_[i]; }
        rs_[0] = S; rq_[0] = Q;
    }
    __syncthreads();
    float mu = rs_[0] * (1.f / 512.f);
    float var = rq_[0] * (1.f / 512.f) - mu * mu;
    float inv = rsqrtf(var + LN_EPS);
    p[t] = (v0 - mu) * inv * gamma[t] + beta[t];
    p[t + 256] = (v1 - mu) * inv * gamma[t + 256] + beta[t + 256];
}

// ---------------- GEMM KV: C[m][c]=xkv[m][:]@Wkv, scatter to k/v buffers ----------------
// M=784, N=1024, K=512; A row-major (g_xr), B row-major (Wkv).
__global__ void gemm_kv(const float* __restrict__ Wkv) {
    __shared__ __align__(16) float As[16][64];
    __shared__ __align__(16) float Bs[16][64];
    int b = blockIdx.z;
    int m0 = blockIdx.y * 64, n0 = blockIdx.x * 64;
    int tid = threadIdx.x;
    int tx = tid & 15, ty = tid >> 4;
    const float* A = g_xr + (long long)b * KTOK * DIMC;
    float acc[4][4] = {};
    int la_m = tid >> 2;            // 0..63
    int la_k = (tid & 3) * 4;       // 0,4,8,12
    int lb_k = tid >> 4;            // 0..15
    int lb_n = (tid & 15) * 4;
    for (int k0 = 0; k0 < DIMC; k0 += 16) {
        float4 av = make_float4(0.f, 0.f, 0.f, 0.f);
        if (m0 + la_m < KTOK)
            av = *(const float4*)&A[(long long)(m0 + la_m) * DIMC + k0 + la_k];
        As[la_k + 0][la_m] = av.x;
        As[la_k + 1][la_m] = av.y;
        As[la_k + 2][la_m] = av.z;
        As[la_k + 3][la_m] = av.w;
        *(float4*)&Bs[lb_k][lb_n] =
            *(const float4*)&Wkv[(long long)(k0 + lb_k) * 1024 + n0 + lb_n];
        __syncthreads();
#pragma unroll
        for (int kk = 0; kk < 16; kk++) {
            float4 a = *(float4*)&As[kk][ty * 4];
            float4 bq = *(float4*)&Bs[kk][tx * 4];
            float avr[4] = {a.x, a.y, a.z, a.w};
            float bvr[4] = {bq.x, bq.y, bq.z, bq.w};
#pragma unroll
            for (int i = 0; i < 4; i++)
#pragma unroll
                for (int j = 0; j < 4; j++) acc[i][j] += avr[i] * bvr[j];
        }
        __syncthreads();
    }
#pragma unroll
    for (int i = 0; i < 4; i++) {
        int m = m0 + ty * 4 + i;
        if (m >= KTOK) continue;
#pragma unroll
        for (int j = 0; j < 4; j++) {
            int n = n0 + tx * 4 + j;            // 0..1023
            int d = n >> 4;                     // HEAD_DIM index
            int h = (n >> 1) & 7;
            int sflag = n & 1;
            long long dst = (((long long)b * NHEADS + h) * KTOK + m) * HD + d;
            if (sflag) g_v[dst] = acc[i][j];
            else       g_k[dst] = acc[i][j];
        }
    }
}

// ---------------- fused attention (flash-style, fp32) ----------------
// grid (98, 32): 32 rows per block, bh per y. 14 KV tiles of 56.
__global__ void attn_kernel() {
    __shared__ __align__(16) float qs[32][64];
    __shared__ __align__(16) float Kt[64][56];   // [d][m]
    __shared__ __align__(16) float Vs[56][64];   // [m][d]
    __shared__ float ps[8][4][56];
    int bh = blockIdx.y;
    int row0 = blockIdx.x * 32;
    int tid = threadIdx.x, lane = tid & 31, warp = tid >> 5;
    const float* qsrc = g_q + ((long long)bh * NTOK + row0) * HD;
    for (int e = tid; e < 32 * 64; e += 256) ((float*)qs)[e] = qsrc[e];

    float run_max[4], run_sum[4];
    float2 acc[4];
#pragma unroll
    for (int r = 0; r < 4; r++) {
        run_max[r] = -INFINITY;
        run_sum[r] = 0.f;
        acc[r] = make_float2(0.f, 0.f);
    }
    const float* kb = g_k + (long long)bh * KTOK * HD;
    const float* vb = g_v + (long long)bh * KTOK * HD;
    int rowg = row0 + warp * 4;
    bool act = lane < 28;

    for (int t = 0; t < 14; t++) {
        int m0 = t * 56;
        __syncthreads();
        for (int e = tid; e < 56 * 64; e += 256) {
            int m = e >> 6, d = e & 63;
            Kt[d][m] = kb[(long long)(m0 + m) * HD + d];
            ((float*)Vs)[e] = vb[(long long)m0 * HD + e];
        }
        __syncthreads();

        // phase A: scores for 4 rows x 56 m (2 m per lane)
        float2 s[4];
#pragma unroll
        for (int r = 0; r < 4; r++) s[r] = make_float2(0.f, 0.f);
        if (act) {
#pragma unroll 16
            for (int d = 0; d < 64; d++) {
                float2 kv = *(float2*)&Kt[d][2 * lane];
#pragma unroll
                for (int r = 0; r < 4; r++) {
                    float qv = qs[warp * 4 + r][d];
                    s[r].x += qv * kv.x;
                    s[r].y += qv * kv.y;
                }
            }
        }
#pragma unroll
        for (int r = 0; r < 4; r++) {
            float sx, sy;
            if (act) {
                const float* bp2 = &g_bias[(long long)(rowg + r) * KTOK + m0 + 2 * lane];
                sx = s[r].x * ATT_SCALE + bp2[0];
                sy = s[r].y * ATT_SCALE + bp2[1];
            } else {
                sx = -INFINITY; sy = -INFINITY;
            }
            float lm = fmaxf(sx, sy);
#pragma unroll
            for (int o = 16; o > 0; o >>= 1)
                lm = fmaxf(lm, __shfl_xor_sync(0xffffffffu, lm, o));
            float nm = fmaxf(run_max[r], lm);
            float corr = __expf(run_max[r] - nm);
            run_max[r] = nm;
            float e0 = act ? __expf(sx - nm) : 0.f;
            float e1 = act ? __expf(sy - nm) : 0.f;
            if (act) {
                ps[warp][r][2 * lane] = e0;
                ps[warp][r][2 * lane + 1] = e1;
            }
            float ls = e0 + e1;
#pragma unroll
            for (int o = 16; o > 0; o >>= 1)
                ls += __shfl_xor_sync(0xffffffffu, ls, o);
            run_sum[r] = run_sum[r] * corr + ls;
            acc[r].x *= corr;
            acc[r].y *= corr;
        }
        __syncwarp();
        // phase B: accumulate P@V (lanes over d, V reads shared by 4 rows)
#pragma unroll 8
        for (int m = 0; m < 56; m++) {
            float2 vv = *(float2*)&Vs[m][2 * lane];
#pragma unroll
            for (int r = 0; r < 4; r++) {
                float p = ps[warp][r][m];
                acc[r].x += p * vv.x;
                acc[r].y += p * vv.y;
            }
        }
        __syncwarp();
    }
    int b = bh >> 3, h = bh & 7;
#pragma unroll
    for (int r = 0; r < 4; r++) {
        float inv = 1.0f / run_sum[r];
        float* op = &g_ao[((long long)b * NTOK + rowg + r) * DIMC + h * HD + 2 * lane];
        *(float2*)op = make_float2(acc[r].x * inv, acc[r].y * inv);
    }
}

// ---------------- GEMM out: [12544,512]@[512,512] + bp, transposed store ----------------
__global__ void gemm_out(const float* __restrict__ Wp, const float* __restrict__ bp,
                         float* __restrict__ out) {
    __shared__ __align__(16) float As[16][64];
    __shared__ __align__(16) float Bs[16][64];
    int m0 = blockIdx.y * 64, n0 = blockIdx.x * 64;
    int tid = threadIdx.x;
    int tx = tid & 15, ty = tid >> 4;
    float acc[4][4] = {};
    int la_m = tid >> 2;
    int la_k = (tid & 3) * 4;
    int lb_k = tid >> 4;
    int lb_n = (tid & 15) * 4;
    for (int k0 = 0; k0 < DIMC; k0 += 16) {
        float4 av = *(const float4*)&g_ao[(long long)(m0 + la_m) * DIMC + k0 + la_k];
        As[la_k + 0][la_m] = av.x;
        As[la_k + 1][la_m] = av.y;
        As[la_k + 2][la_m] = av.z;
        As[la_k + 3][la_m] = av.w;
        *(float4*)&Bs[lb_k][lb_n] =
            *(const float4*)&Wp[(long long)(k0 + lb_k) * DIMC + n0 + lb_n];
        __syncthreads();
#pragma unroll
        for (int kk = 0; kk < 16; kk++) {
            float4 a = *(float4*)&As[kk][ty * 4];
            float4 bq = *(float4*)&Bs[kk][tx * 4];
            float avr[4] = {a.x, a.y, a.z, a.w};
            float bvr[4] = {bq.x, bq.y, bq.z, bq.w};
#pragma unroll
            for (int i = 0; i < 4; i++)
#pragma unroll
                for (int j = 0; j < 4; j++) acc[i][j] += avr[i] * bvr[j];
        }
        __syncthreads();
    }
#pragma unroll
    for (int i = 0; i < 4; i++) {
        int m = m0 + ty * 4 + i;        // global row over B*NTOK
        int b = m / NTOK;
        int n = m - b * NTOK;
#pragma unroll
        for (int j = 0; j < 4; j++) {
            int c = n0 + tx * 4 + j;
            out[((long long)b * DIMC + c) * NTOK + n] = acc[i][j] + bp[c];
        }
    }
}

// ---------------- launch ----------------
extern "C" void kernel_launch(void* const* d_in, const int* in_sizes, int n_in,
                              void* d_out, int out_size) {
    const float* x     = (const float*)d_in[0];
    const float* Wq    = (const float*)d_in[1];
    const float* Wkv   = (const float*)d_in[2];
    const float* Wsr   = (const float*)d_in[3];
    const float* b_sr  = (const float*)d_in[4];
    const float* gamma = (const float*)d_in[5];
    const float* beta  = (const float*)d_in[6];
    const float* Wp    = (const float*)d_in[7];
    const float* bp    = (const float*)d_in[8];
    const float* pos   = (const float*)d_in[9];
    const int*   rel   = (const int*)d_in[10];
    float* out = (float*)d_out;

    bias_kernel<<<(NTOK * KTOK + 255) / 256, 256>>>(pos, rel);
    gemm_q<<<dim3(8, 49, BATCH), 256>>>(x, Wq);
    gemm_conv<<<dim3(8, 13, BATCH), 256>>>(x, Wsr, b_sr);
    ln_kernel<<<BATCH * KTOK, 256>>>(gamma, beta);
    gemm_kv<<<dim3(16, 13, BATCH), 256>>>(Wkv);
    attn_kernel<<<dim3(98, 32), 256>>>();
    gemm_out<<<dim3(8, 196, 1), 256>>>(Wp, bp, out);
}